// round 4
// baseline (speedup 1.0000x reference)
#include <cuda_runtime.h>
#include <cuda_fp16.h>
#include <cstdint>

#define N_NODES 50000
#define N_EDGES 800000

// ---------------- scratch (device globals; no allocation allowed) ----------
__device__ int    g_is64;
__device__ int    g_cnt[N_NODES];
__device__ int    g_fill[N_NODES];
__device__ int    g_rowptr[N_NODES + 1];
__device__ int2   g_cw[N_EDGES];               // (src, weight-bits)
__device__ float  g_dinv[N_NODES];
__device__ float  g_Af[(size_t)N_NODES * 128]; // fp32: A1, later H3
__device__ __half g_Hh[(size_t)N_NODES * 128]; // fp16: H1, later H2
__device__ __half g_Bh[(size_t)N_NODES * 64];  // fp16: A2

// ---------------- edge-index dtype sniffing --------------------------------
__device__ __forceinline__ int load_idx(const void* ei, long long pos) {
    if (g_is64) return (int)((const long long*)ei)[pos];
    return ((const int*)ei)[pos];
}

// ---------------- preprocessing ---------------------------------------------
__global__ void k_zero(const void* ei) {
    int i = blockIdx.x * blockDim.x + threadIdx.x;
    if (i < N_NODES) g_cnt[i] = 0;
    if (i == 0) {
        const unsigned long long* p = (const unsigned long long*)ei;
        int ok = 1;
        for (int k = 0; k < 16; k++)
            if (p[k] >= (unsigned long long)N_NODES) ok = 0;
        g_is64 = ok;
    }
}

__global__ void k_hist(const void* ei) {
    int e = blockIdx.x * blockDim.x + threadIdx.x;
    if (e < N_EDGES) {
        int d = load_idx(ei, (long long)N_EDGES + e);
        atomicAdd(&g_cnt[d], 1);
    }
}

// single block: serial-chunk scan + dinv + fill-init + rowptr[N]
__global__ void k_scan() {
    __shared__ int sh[1024];
    int t = threadIdx.x;
    int base = t * 49;
    int end = min(base + 49, N_NODES);
    int sum = 0;
    for (int i = base; i < end; i++) sum += g_cnt[i];
    sh[t] = sum;
    __syncthreads();
    for (int off = 1; off < 1024; off <<= 1) {
        int v = (t >= off) ? sh[t - off] : 0;
        __syncthreads();
        sh[t] += v;
        __syncthreads();
    }
    int run = (t > 0) ? sh[t - 1] : 0;
    for (int i = base; i < end; i++) {
        int c = g_cnt[i];
        g_rowptr[i] = run;
        g_fill[i]   = run;                    // atomic fill cursor starts at rowptr
        run += c;
        g_dinv[i] = rsqrtf((float)(c + 1));   // +1 self loop
    }
    if (t == 1023) g_rowptr[N_NODES] = run;
}

__global__ void k_fill(const void* ei) {
    int e = blockIdx.x * blockDim.x + threadIdx.x;
    if (e < N_EDGES) {
        int s = load_idx(ei, e);
        int d = load_idx(ei, (long long)N_EDGES + e);
        int pos = atomicAdd(&g_fill[d], 1);
        float w = g_dinv[s] * g_dinv[d];
        g_cw[pos] = make_int2(s, __float_as_int(w));
    }
}

// ---------------- dense GEMM: Y[N,NO] = X[N,K] @ W[K,NO] (+bias) ----------
// 256 threads; tile RB x NO (RB*NO = 8192); K chunks of 32; fp32x2 FMA.
// OUTH: convert result to fp16 on store.
template <int K, int NO, bool BIAS, bool OUTH>
__global__ void __launch_bounds__(256) k_gemm(const float* __restrict__ X,
                                              const float* __restrict__ W,
                                              const float* __restrict__ bias,
                                              void* __restrict__ Yout) {
    constexpr int RB = 8192 / NO;
    constexpr int KC = 32;
    constexpr int XS = RB + 4;
    __shared__ float Wsh[KC * NO];
    __shared__ float Xsh[KC * XS];

    int tid = threadIdx.x;
    int rg = tid & (RB / 4 - 1);
    int cg = tid / (RB / 4);
    long long r0 = (long long)blockIdx.x * RB;

    unsigned long long acc[4][4];
#pragma unroll
    for (int r = 0; r < 4; r++)
#pragma unroll
        for (int c = 0; c < 4; c++) acc[r][c] = 0ull;

    for (int kc = 0; kc < K; kc += KC) {
        __syncthreads();
        const float4* W4 = (const float4*)(W + kc * NO);
        float4* Wsh4 = (float4*)Wsh;
#pragma unroll
        for (int i = tid; i < KC * NO / 4; i += 256) Wsh4[i] = W4[i];
#pragma unroll
        for (int i = tid; i < RB * KC; i += 256) {
            int r = i >> 5, k = i & 31;
            long long row = r0 + r;
            if (row >= N_NODES) row = 0;
            Xsh[k * XS + r] = X[row * K + kc + k];
        }
        __syncthreads();

#pragma unroll 8
        for (int k = 0; k < KC; k++) {
            float4 xv = *(const float4*)(Xsh + k * XS + 4 * rg);
            unsigned long long xd[4];
            asm("mov.b64 %0, {%1, %1};" : "=l"(xd[0]) : "f"(xv.x));
            asm("mov.b64 %0, {%1, %1};" : "=l"(xd[1]) : "f"(xv.y));
            asm("mov.b64 %0, {%1, %1};" : "=l"(xd[2]) : "f"(xv.z));
            asm("mov.b64 %0, {%1, %1};" : "=l"(xd[3]) : "f"(xv.w));
            const unsigned long long* wp =
                (const unsigned long long*)(Wsh + k * NO + 8 * cg);
            unsigned long long w0 = wp[0], w1 = wp[1], w2 = wp[2], w3 = wp[3];
#pragma unroll
            for (int r = 0; r < 4; r++) {
                asm("fma.rn.f32x2 %0, %1, %2, %0;" : "+l"(acc[r][0]) : "l"(xd[r]), "l"(w0));
                asm("fma.rn.f32x2 %0, %1, %2, %0;" : "+l"(acc[r][1]) : "l"(xd[r]), "l"(w1));
                asm("fma.rn.f32x2 %0, %1, %2, %0;" : "+l"(acc[r][2]) : "l"(xd[r]), "l"(w2));
                asm("fma.rn.f32x2 %0, %1, %2, %0;" : "+l"(acc[r][3]) : "l"(xd[r]), "l"(w3));
            }
        }
    }

    float bv[8];
#pragma unroll
    for (int c = 0; c < 8; c++) bv[c] = BIAS ? bias[8 * cg + c] : 0.0f;
#pragma unroll
    for (int r = 0; r < 4; r++) {
        long long row = r0 + 4 * rg + r;
        if (row < N_NODES) {
            if constexpr (OUTH) {
                __half2* yp = ((__half2*)((__half*)Yout + row * NO)) + 4 * cg;
#pragma unroll
                for (int c = 0; c < 4; c++) {
                    float lo = __uint_as_float((unsigned)acc[r][c]);
                    float hi = __uint_as_float((unsigned)(acc[r][c] >> 32));
                    yp[c] = __floats2half2_rn(lo + bv[2 * c], hi + bv[2 * c + 1]);
                }
            } else {
                float* yp = (float*)Yout + row * NO + 8 * cg;
#pragma unroll
                for (int c = 0; c < 4; c++) {
                    float lo = __uint_as_float((unsigned)acc[r][c]);
                    float hi = __uint_as_float((unsigned)(acc[r][c] >> 32));
                    ((float2*)yp)[c] = make_float2(lo + bv[2 * c], hi + bv[2 * c + 1]);
                }
            }
        }
    }
}

// ---------------- sparse aggregation (fp16 gather): one warp per node ------
// out[i] = (relu?)( sum w_e * H[src_e] + dinv[i]^2 * H[i] (+ b) )
// 8 gathers in flight per warp; fp32 accumulate; optional fp16 output.
template <int F, bool RELU, bool BIAS, bool OUTH>
__global__ void k_agg(const __half* __restrict__ H, const float* __restrict__ b,
                      void* __restrict__ outp) {
    int gw   = (blockIdx.x * blockDim.x + threadIdx.x) >> 5;
    int lane = threadIdx.x & 31;
    if (gw >= N_NODES) return;
    int s = g_rowptr[gw], e = g_rowptr[gw + 1];

    if constexpr (F == 128) {
        float4 a0 = make_float4(0.f, 0.f, 0.f, 0.f);
        float4 a1 = make_float4(0.f, 0.f, 0.f, 0.f);
        int j = s;
        for (; j + 8 <= e; j += 8) {
            int2 cw[8];
            uint2 v[8];
#pragma unroll
            for (int q = 0; q < 8; q++) cw[q] = __ldg(&g_cw[j + q]);
#pragma unroll
            for (int q = 0; q < 8; q++)
                v[q] = __ldg(((const uint2*)(H + (size_t)cw[q].x * 128)) + lane);
#pragma unroll
            for (int q = 0; q < 8; q++) {
                float w = __int_as_float(cw[q].y);
                float2 f0 = __half22float2(*(__half2*)&v[q].x);
                float2 f1 = __half22float2(*(__half2*)&v[q].y);
                float4& a = (q & 1) ? a1 : a0;
                a.x = fmaf(w, f0.x, a.x); a.y = fmaf(w, f0.y, a.y);
                a.z = fmaf(w, f1.x, a.z); a.w = fmaf(w, f1.y, a.w);
            }
        }
        for (; j < e; j++) {
            int2 cw = __ldg(&g_cw[j]);
            float w = __int_as_float(cw.y);
            uint2 v = __ldg(((const uint2*)(H + (size_t)cw.x * 128)) + lane);
            float2 f0 = __half22float2(*(__half2*)&v.x);
            float2 f1 = __half22float2(*(__half2*)&v.y);
            a0.x = fmaf(w, f0.x, a0.x); a0.y = fmaf(w, f0.y, a0.y);
            a0.z = fmaf(w, f1.x, a0.z); a0.w = fmaf(w, f1.y, a0.w);
        }
        float di = g_dinv[gw];
        float wl = di * di;
        uint2 vs = ((const uint2*)(H + (size_t)gw * 128))[lane];
        float2 s0 = __half22float2(*(__half2*)&vs.x);
        float2 s1 = __half22float2(*(__half2*)&vs.y);
        a0.x = fmaf(wl, s0.x, a0.x); a0.y = fmaf(wl, s0.y, a0.y);
        a0.z = fmaf(wl, s1.x, a0.z); a0.w = fmaf(wl, s1.y, a0.w);
        a0.x += a1.x; a0.y += a1.y; a0.z += a1.z; a0.w += a1.w;
        if (BIAS) {
            float4 bb = ((const float4*)b)[lane];
            a0.x += bb.x; a0.y += bb.y; a0.z += bb.z; a0.w += bb.w;
        }
        if (RELU) {
            a0.x = fmaxf(a0.x, 0.f); a0.y = fmaxf(a0.y, 0.f);
            a0.z = fmaxf(a0.z, 0.f); a0.w = fmaxf(a0.w, 0.f);
        }
        if constexpr (OUTH) {
            uint2 o;
            *(__half2*)&o.x = __floats2half2_rn(a0.x, a0.y);
            *(__half2*)&o.y = __floats2half2_rn(a0.z, a0.w);
            ((uint2*)((__half*)outp + (size_t)gw * 128))[lane] = o;
        } else {
            ((float4*)((float*)outp + (size_t)gw * 128))[lane] = a0;
        }
    } else { // F == 64
        float2 a0 = make_float2(0.f, 0.f);
        float2 a1 = make_float2(0.f, 0.f);
        int j = s;
        for (; j + 8 <= e; j += 8) {
            int2 cw[8];
            unsigned v[8];
#pragma unroll
            for (int q = 0; q < 8; q++) cw[q] = __ldg(&g_cw[j + q]);
#pragma unroll
            for (int q = 0; q < 8; q++)
                v[q] = __ldg(((const unsigned*)(H + (size_t)cw[q].x * 64)) + lane);
#pragma unroll
            for (int q = 0; q < 8; q++) {
                float w = __int_as_float(cw[q].y);
                float2 f = __half22float2(*(__half2*)&v[q]);
                float2& a = (q & 1) ? a1 : a0;
                a.x = fmaf(w, f.x, a.x); a.y = fmaf(w, f.y, a.y);
            }
        }
        for (; j < e; j++) {
            int2 cw = __ldg(&g_cw[j]);
            float w = __int_as_float(cw.y);
            unsigned v = __ldg(((const unsigned*)(H + (size_t)cw.x * 64)) + lane);
            float2 f = __half22float2(*(__half2*)&v);
            a0.x = fmaf(w, f.x, a0.x); a0.y = fmaf(w, f.y, a0.y);
        }
        float di = g_dinv[gw];
        float wl = di * di;
        unsigned vs = ((const unsigned*)(H + (size_t)gw * 64))[lane];
        float2 sf = __half22float2(*(__half2*)&vs);
        a0.x = fmaf(wl, sf.x, a0.x); a0.y = fmaf(wl, sf.y, a0.y);
        a0.x += a1.x; a0.y += a1.y;
        if (BIAS) {
            float2 bb = ((const float2*)b)[lane];
            a0.x += bb.x; a0.y += bb.y;
        }
        if (RELU) { a0.x = fmaxf(a0.x, 0.f); a0.y = fmaxf(a0.y, 0.f); }
        if constexpr (OUTH) {
            unsigned o;
            *(__half2*)&o = __floats2half2_rn(a0.x, a0.y);
            ((unsigned*)((__half*)outp + (size_t)gw * 64))[lane] = o;
        } else {
            ((float2*)((float*)outp + (size_t)gw * 64))[lane] = a0;
        }
    }
}

// ---------------- launch ----------------------------------------------------
extern "C" void kernel_launch(void* const* d_in, const int* in_sizes, int n_in,
                              void* d_out, int out_size) {
    const float* x  = (const float*)d_in[0];
    const void*  ei = d_in[1];
    const float* W1 = (const float*)d_in[2];
    const float* b1 = (const float*)d_in[3];
    const float* W2 = (const float*)d_in[4];
    const float* b2 = (const float*)d_in[5];
    const float* W3 = (const float*)d_in[6];
    const float* b3 = (const float*)d_in[7];
    float* out = (float*)d_out;

    void *pAf = nullptr, *pHh = nullptr, *pBh = nullptr;
    cudaGetSymbolAddress(&pAf, g_Af);
    cudaGetSymbolAddress(&pHh, g_Hh);
    cudaGetSymbolAddress(&pBh, g_Bh);
    float*  Af = (float*)pAf;
    __half* Hh = (__half*)pHh;
    __half* Bh = (__half*)pBh;

    const int TB = 256;
    int gN = (N_NODES + TB - 1) / TB;
    int gE = (N_EDGES + TB - 1) / TB;
    int aggBlocks = (N_NODES * 32 + TB - 1) / TB;
    int g64  = (N_NODES + 63) / 64;
    int g128 = (N_NODES + 127) / 128;

    // preprocessing: degree norm + CSR(dst)
    k_zero<<<gN, TB>>>(ei);
    k_hist<<<gE, TB>>>(ei);
    k_scan<<<1, 1024>>>();
    k_fill<<<gE, TB>>>(ei);

    // layer 1: relu(agg(x@W1) + b1)   [H1 fp16 -> A1 fp32]
    k_gemm<128, 128, false, true><<<g64, 256>>>(x, W1, nullptr, Hh);
    k_agg<128, true, true, false><<<aggBlocks, TB>>>(Hh, b1, Af);
    // layer 2: relu(agg(A1@W2) + b2)  [H2 fp16 -> A2 fp16]
    k_gemm<128, 64, false, true><<<g128, 256>>>(Af, W2, nullptr, Hh);
    k_agg<64, true, true, true><<<aggBlocks, TB>>>(Hh, b2, Bh);
    // layer 3 (agg is linear): out = agg(A2) @ W3 + b3   [H3 fp32]
    k_agg<64, false, false, false><<<aggBlocks, TB>>>(Bh, nullptr, Af);
    k_gemm<64, 128, true, false><<<g64, 256>>>(Af, W3, b3, out);
}

// round 5
// speedup vs baseline: 1.3473x; 1.3473x over previous
#include <cuda_runtime.h>
#include <cuda_fp16.h>
#include <cstdint>

#define N_NODES 50000
#define N_EDGES 800000

// ---------------- scratch (device globals; no allocation allowed) ----------
__device__ int    g_is64;
__device__ int    g_cnt[N_NODES];
__device__ int    g_fill[N_NODES];
__device__ int    g_rowptr[N_NODES + 1];
__device__ int2   g_cw[N_EDGES];               // (src, weight-bits)
__device__ float  g_dinv[N_NODES];
__device__ float  g_Af[(size_t)N_NODES * 128]; // fp32: A1, later H3
__device__ __half g_Hh[(size_t)N_NODES * 128]; // fp16: H1, later H2
__device__ __half g_Bh[(size_t)N_NODES * 64];  // fp16: A2

// ---------------- edge-index dtype sniffing --------------------------------
__device__ __forceinline__ int load_idx(const void* ei, long long pos) {
    if (g_is64) return (int)((const long long*)ei)[pos];
    return ((const int*)ei)[pos];
}

// ---------------- preprocessing ---------------------------------------------
__global__ void k_zero(const void* ei) {
    int i = blockIdx.x * blockDim.x + threadIdx.x;
    if (i < N_NODES) g_cnt[i] = 0;
    if (i == 0) {
        const unsigned long long* p = (const unsigned long long*)ei;
        int ok = 1;
        for (int k = 0; k < 16; k++)
            if (p[k] >= (unsigned long long)N_NODES) ok = 0;
        g_is64 = ok;
    }
}

__global__ void k_hist(const void* ei) {
    int e = blockIdx.x * blockDim.x + threadIdx.x;
    if (e < N_EDGES) {
        int d = load_idx(ei, (long long)N_EDGES + e);
        atomicAdd(&g_cnt[d], 1);
    }
}

// single block, COALESCED tiled scan: exclusive prefix of g_cnt -> rowptr,
// fill cursor init, dinv. Tile = 1024 elements, warp-shuffle scans.
__global__ void k_scan() {
    __shared__ int wsum[32];
    __shared__ int s_carry;
    int t = threadIdx.x, lane = t & 31, wid = t >> 5;
    if (t == 0) s_carry = 0;
    __syncthreads();

    for (int base = 0; base < N_NODES; base += 1024) {
        int i = base + t;
        int c = (i < N_NODES) ? g_cnt[i] : 0;
        // warp inclusive scan
        int v = c;
#pragma unroll
        for (int off = 1; off < 32; off <<= 1) {
            int u = __shfl_up_sync(0xffffffffu, v, off);
            if (lane >= off) v += u;
        }
        if (lane == 31) wsum[wid] = v;
        __syncthreads();
        if (wid == 0) {
            int w = wsum[lane];
#pragma unroll
            for (int off = 1; off < 32; off <<= 1) {
                int u = __shfl_up_sync(0xffffffffu, w, off);
                if (lane >= off) w += u;
            }
            wsum[lane] = w;
        }
        __syncthreads();
        int woff = (wid > 0) ? wsum[wid - 1] : 0;
        int carry = s_carry;
        int incl = v + woff + carry;
        int excl = incl - c;
        if (i < N_NODES) {
            g_rowptr[i] = excl;
            g_fill[i]   = excl;                  // atomic fill cursor
            g_dinv[i]   = rsqrtf((float)(c + 1)); // +1 self loop
        }
        __syncthreads();                          // all reads of s_carry done
        if (t == 1023) s_carry = incl;
        __syncthreads();
    }
    if (t == 0) g_rowptr[N_NODES] = s_carry;
}

__global__ void k_fill(const void* ei) {
    int e = blockIdx.x * blockDim.x + threadIdx.x;
    if (e < N_EDGES) {
        int s = load_idx(ei, e);
        int d = load_idx(ei, (long long)N_EDGES + e);
        int pos = atomicAdd(&g_fill[d], 1);
        float w = g_dinv[s] * g_dinv[d];
        g_cw[pos] = make_int2(s, __float_as_int(w));
    }
}

// ---------------- dense GEMM: Y[N,NO] = X[N,K] @ W[K,NO] (+bias) ----------
template <int K, int NO, bool BIAS, bool OUTH>
__global__ void __launch_bounds__(256) k_gemm(const float* __restrict__ X,
                                              const float* __restrict__ W,
                                              const float* __restrict__ bias,
                                              void* __restrict__ Yout) {
    constexpr int RB = 8192 / NO;
    constexpr int KC = 32;
    constexpr int XS = RB + 4;
    __shared__ float Wsh[KC * NO];
    __shared__ float Xsh[KC * XS];

    int tid = threadIdx.x;
    int rg = tid & (RB / 4 - 1);
    int cg = tid / (RB / 4);
    long long r0 = (long long)blockIdx.x * RB;

    unsigned long long acc[4][4];
#pragma unroll
    for (int r = 0; r < 4; r++)
#pragma unroll
        for (int c = 0; c < 4; c++) acc[r][c] = 0ull;

    for (int kc = 0; kc < K; kc += KC) {
        __syncthreads();
        const float4* W4 = (const float4*)(W + kc * NO);
        float4* Wsh4 = (float4*)Wsh;
#pragma unroll
        for (int i = tid; i < KC * NO / 4; i += 256) Wsh4[i] = W4[i];
#pragma unroll
        for (int i = tid; i < RB * KC; i += 256) {
            int r = i >> 5, k = i & 31;
            long long row = r0 + r;
            if (row >= N_NODES) row = 0;
            Xsh[k * XS + r] = X[row * K + kc + k];
        }
        __syncthreads();

#pragma unroll 8
        for (int k = 0; k < KC; k++) {
            float4 xv = *(const float4*)(Xsh + k * XS + 4 * rg);
            unsigned long long xd[4];
            asm("mov.b64 %0, {%1, %1};" : "=l"(xd[0]) : "f"(xv.x));
            asm("mov.b64 %0, {%1, %1};" : "=l"(xd[1]) : "f"(xv.y));
            asm("mov.b64 %0, {%1, %1};" : "=l"(xd[2]) : "f"(xv.z));
            asm("mov.b64 %0, {%1, %1};" : "=l"(xd[3]) : "f"(xv.w));
            const unsigned long long* wp =
                (const unsigned long long*)(Wsh + k * NO + 8 * cg);
            unsigned long long w0 = wp[0], w1 = wp[1], w2 = wp[2], w3 = wp[3];
#pragma unroll
            for (int r = 0; r < 4; r++) {
                asm("fma.rn.f32x2 %0, %1, %2, %0;" : "+l"(acc[r][0]) : "l"(xd[r]), "l"(w0));
                asm("fma.rn.f32x2 %0, %1, %2, %0;" : "+l"(acc[r][1]) : "l"(xd[r]), "l"(w1));
                asm("fma.rn.f32x2 %0, %1, %2, %0;" : "+l"(acc[r][2]) : "l"(xd[r]), "l"(w2));
                asm("fma.rn.f32x2 %0, %1, %2, %0;" : "+l"(acc[r][3]) : "l"(xd[r]), "l"(w3));
            }
        }
    }

    float bv[8];
#pragma unroll
    for (int c = 0; c < 8; c++) bv[c] = BIAS ? bias[8 * cg + c] : 0.0f;
#pragma unroll
    for (int r = 0; r < 4; r++) {
        long long row = r0 + 4 * rg + r;
        if (row < N_NODES) {
            if constexpr (OUTH) {
                __half2* yp = ((__half2*)((__half*)Yout + row * NO)) + 4 * cg;
#pragma unroll
                for (int c = 0; c < 4; c++) {
                    float lo = __uint_as_float((unsigned)acc[r][c]);
                    float hi = __uint_as_float((unsigned)(acc[r][c] >> 32));
                    yp[c] = __floats2half2_rn(lo + bv[2 * c], hi + bv[2 * c + 1]);
                }
            } else {
                float* yp = (float*)Yout + row * NO + 8 * cg;
#pragma unroll
                for (int c = 0; c < 4; c++) {
                    float lo = __uint_as_float((unsigned)acc[r][c]);
                    float hi = __uint_as_float((unsigned)(acc[r][c] >> 32));
                    ((float2*)yp)[c] = make_float2(lo + bv[2 * c], hi + bv[2 * c + 1]);
                }
            }
        }
    }
}

// ---------------- sparse aggregation (fp16 gather): one warp per node ------
template <int F, bool RELU, bool BIAS, bool OUTH>
__global__ void k_agg(const __half* __restrict__ H, const float* __restrict__ b,
                      void* __restrict__ outp) {
    int gw   = (blockIdx.x * blockDim.x + threadIdx.x) >> 5;
    int lane = threadIdx.x & 31;
    if (gw >= N_NODES) return;
    int s = g_rowptr[gw], e = g_rowptr[gw + 1];

    if constexpr (F == 128) {
        float4 a0 = make_float4(0.f, 0.f, 0.f, 0.f);
        float4 a1 = make_float4(0.f, 0.f, 0.f, 0.f);
        int j = s;
        for (; j + 8 <= e; j += 8) {
            int2 cw[8];
            uint2 v[8];
#pragma unroll
            for (int q = 0; q < 8; q++) cw[q] = __ldg(&g_cw[j + q]);
#pragma unroll
            for (int q = 0; q < 8; q++)
                v[q] = __ldg(((const uint2*)(H + (size_t)cw[q].x * 128)) + lane);
#pragma unroll
            for (int q = 0; q < 8; q++) {
                float w = __int_as_float(cw[q].y);
                float2 f0 = __half22float2(*(__half2*)&v[q].x);
                float2 f1 = __half22float2(*(__half2*)&v[q].y);
                float4& a = (q & 1) ? a1 : a0;
                a.x = fmaf(w, f0.x, a.x); a.y = fmaf(w, f0.y, a.y);
                a.z = fmaf(w, f1.x, a.z); a.w = fmaf(w, f1.y, a.w);
            }
        }
        for (; j < e; j++) {
            int2 cw = __ldg(&g_cw[j]);
            float w = __int_as_float(cw.y);
            uint2 v = __ldg(((const uint2*)(H + (size_t)cw.x * 128)) + lane);
            float2 f0 = __half22float2(*(__half2*)&v.x);
            float2 f1 = __half22float2(*(__half2*)&v.y);
            a0.x = fmaf(w, f0.x, a0.x); a0.y = fmaf(w, f0.y, a0.y);
            a0.z = fmaf(w, f1.x, a0.z); a0.w = fmaf(w, f1.y, a0.w);
        }
        float di = g_dinv[gw];
        float wl = di * di;
        uint2 vs = ((const uint2*)(H + (size_t)gw * 128))[lane];
        float2 s0 = __half22float2(*(__half2*)&vs.x);
        float2 s1 = __half22float2(*(__half2*)&vs.y);
        a0.x = fmaf(wl, s0.x, a0.x); a0.y = fmaf(wl, s0.y, a0.y);
        a0.z = fmaf(wl, s1.x, a0.z); a0.w = fmaf(wl, s1.y, a0.w);
        a0.x += a1.x; a0.y += a1.y; a0.z += a1.z; a0.w += a1.w;
        if (BIAS) {
            float4 bb = ((const float4*)b)[lane];
            a0.x += bb.x; a0.y += bb.y; a0.z += bb.z; a0.w += bb.w;
        }
        if (RELU) {
            a0.x = fmaxf(a0.x, 0.f); a0.y = fmaxf(a0.y, 0.f);
            a0.z = fmaxf(a0.z, 0.f); a0.w = fmaxf(a0.w, 0.f);
        }
        if constexpr (OUTH) {
            uint2 o;
            *(__half2*)&o.x = __floats2half2_rn(a0.x, a0.y);
            *(__half2*)&o.y = __floats2half2_rn(a0.z, a0.w);
            ((uint2*)((__half*)outp + (size_t)gw * 128))[lane] = o;
        } else {
            ((float4*)((float*)outp + (size_t)gw * 128))[lane] = a0;
        }
    } else { // F == 64
        float2 a0 = make_float2(0.f, 0.f);
        float2 a1 = make_float2(0.f, 0.f);
        int j = s;
        for (; j + 8 <= e; j += 8) {
            int2 cw[8];
            unsigned v[8];
#pragma unroll
            for (int q = 0; q < 8; q++) cw[q] = __ldg(&g_cw[j + q]);
#pragma unroll
            for (int q = 0; q < 8; q++)
                v[q] = __ldg(((const unsigned*)(H + (size_t)cw[q].x * 64)) + lane);
#pragma unroll
            for (int q = 0; q < 8; q++) {
                float w = __int_as_float(cw[q].y);
                float2 f = __half22float2(*(__half2*)&v[q]);
                float2& a = (q & 1) ? a1 : a0;
                a.x = fmaf(w, f.x, a.x); a.y = fmaf(w, f.y, a.y);
            }
        }
        for (; j < e; j++) {
            int2 cw = __ldg(&g_cw[j]);
            float w = __int_as_float(cw.y);
            unsigned v = __ldg(((const unsigned*)(H + (size_t)cw.x * 64)) + lane);
            float2 f = __half22float2(*(__half2*)&v);
            a0.x = fmaf(w, f.x, a0.x); a0.y = fmaf(w, f.y, a0.y);
        }
        float di = g_dinv[gw];
        float wl = di * di;
        unsigned vs = ((const unsigned*)(H + (size_t)gw * 64))[lane];
        float2 sf = __half22float2(*(__half2*)&vs);
        a0.x = fmaf(wl, sf.x, a0.x); a0.y = fmaf(wl, sf.y, a0.y);
        a0.x += a1.x; a0.y += a1.y;
        if (BIAS) {
            float2 bb = ((const float2*)b)[lane];
            a0.x += bb.x; a0.y += bb.y;
        }
        if (RELU) { a0.x = fmaxf(a0.x, 0.f); a0.y = fmaxf(a0.y, 0.f); }
        if constexpr (OUTH) {
            unsigned o;
            *(__half2*)&o = __floats2half2_rn(a0.x, a0.y);
            ((unsigned*)((__half*)outp + (size_t)gw * 64))[lane] = o;
        } else {
            ((float2*)((float*)outp + (size_t)gw * 64))[lane] = a0;
        }
    }
}

// ---------------- launch ----------------------------------------------------
extern "C" void kernel_launch(void* const* d_in, const int* in_sizes, int n_in,
                              void* d_out, int out_size) {
    const float* x  = (const float*)d_in[0];
    const void*  ei = d_in[1];
    const float* W1 = (const float*)d_in[2];
    const float* b1 = (const float*)d_in[3];
    const float* W2 = (const float*)d_in[4];
    const float* b2 = (const float*)d_in[5];
    const float* W3 = (const float*)d_in[6];
    const float* b3 = (const float*)d_in[7];
    float* out = (float*)d_out;

    void *pAf = nullptr, *pHh = nullptr, *pBh = nullptr;
    cudaGetSymbolAddress(&pAf, g_Af);
    cudaGetSymbolAddress(&pHh, g_Hh);
    cudaGetSymbolAddress(&pBh, g_Bh);
    float*  Af = (float*)pAf;
    __half* Hh = (__half*)pHh;
    __half* Bh = (__half*)pBh;

    const int TB = 256;
    int gN = (N_NODES + TB - 1) / TB;
    int gE = (N_EDGES + TB - 1) / TB;
    int aggBlocks = (N_NODES * 32 + TB - 1) / TB;
    int g64  = (N_NODES + 63) / 64;
    int g128 = (N_NODES + 127) / 128;

    // preprocessing: degree norm + CSR(dst)
    k_zero<<<gN, TB>>>(ei);
    k_hist<<<gE, TB>>>(ei);
    k_scan<<<1, 1024>>>();
    k_fill<<<gE, TB>>>(ei);

    // layer 1: relu(agg(x@W1) + b1)   [H1 fp16 -> A1 fp32]
    k_gemm<128, 128, false, true><<<g64, 256>>>(x, W1, nullptr, Hh);
    k_agg<128, true, true, false><<<aggBlocks, TB>>>(Hh, b1, Af);
    // layer 2: relu(agg(A1@W2) + b2)  [H2 fp16 -> A2 fp16]
    k_gemm<128, 64, false, true><<<g128, 256>>>(Af, W2, nullptr, Hh);
    k_agg<64, true, true, true><<<aggBlocks, TB>>>(Hh, b2, Bh);
    // layer 3 (agg is linear): out = agg(A2) @ W3 + b3   [H3 fp32]
    k_agg<64, false, false, false><<<aggBlocks, TB>>>(Bh, nullptr, Af);
    k_gemm<64, 128, true, false><<<g64, 256>>>(Af, W3, b3, out);
}